// round 4
// baseline (speedup 1.0000x reference)
#include <cuda_runtime.h>

#define B_CONST 8192
#define D_CONST 4096
#define MARGIN 0.5f
#define THREADS 256

__global__ void zero_out_kernel(float* out) {
    out[0] = 0.0f;
}

// 256-bit global load with L2 evict_last hint (sm_100 requires v8.b32 width
// for this modifier). Keeps the 128MB feature matrix ~resident in the 126MB L2
// across graph replays instead of LRU-thrashing it.
__device__ __forceinline__ void ldg256_evict_last(const float* p, float v[8]) {
    unsigned r0, r1, r2, r3, r4, r5, r6, r7;
    asm volatile(
        "ld.global.nc.L2::evict_last.v8.b32 {%0,%1,%2,%3,%4,%5,%6,%7}, [%8];"
        : "=r"(r0), "=r"(r1), "=r"(r2), "=r"(r3),
          "=r"(r4), "=r"(r5), "=r"(r6), "=r"(r7)
        : "l"(p));
    v[0] = __uint_as_float(r0); v[1] = __uint_as_float(r1);
    v[2] = __uint_as_float(r2); v[3] = __uint_as_float(r3);
    v[4] = __uint_as_float(r4); v[5] = __uint_as_float(r5);
    v[6] = __uint_as_float(r6); v[7] = __uint_as_float(r7);
}

__global__ __launch_bounds__(THREADS) void triplet_loss_kernel(
    const float* __restrict__ feats,
    const float* __restrict__ label,
    const int* __restrict__ idx1,
    const int* __restrict__ idx2,
    float* __restrict__ out)
{
    const int b = blockIdx.x;
    const int tid = threadIdx.x;

    const int i1 = idx1[b];
    const int i2 = idx2[b];

    const float* __restrict__ a  = feats + (long long)b  * D_CONST;
    const float* __restrict__ t1 = feats + (long long)i1 * D_CONST;
    const float* __restrict__ t2 = feats + (long long)i2 * D_CONST;

    float s_abs1 = 0.f, s_abs2 = 0.f, s_sq1 = 0.f, s_sq2 = 0.f;

    const int NC = D_CONST / 8;  // 512 chunks of 8 floats per row
    #pragma unroll
    for (int i = tid; i < NC; i += THREADS) {
        const int off = i * 8;
        float av[8], v1[8], v2[8];
        ldg256_evict_last(a  + off, av);
        ldg256_evict_last(t1 + off, v1);
        ldg256_evict_last(t2 + off, v2);

        #pragma unroll
        for (int j = 0; j < 8; j++) {
            float d1 = av[j] - v1[j];
            float d2 = av[j] - v2[j];
            s_abs1 += fabsf(d1); s_sq1 = fmaf(d1, d1, s_sq1);
            s_abs2 += fabsf(d2); s_sq2 = fmaf(d2, d2, s_sq2);
        }
    }

    // warp reduce
    #pragma unroll
    for (int off = 16; off > 0; off >>= 1) {
        s_abs1 += __shfl_down_sync(0xFFFFFFFF, s_abs1, off);
        s_abs2 += __shfl_down_sync(0xFFFFFFFF, s_abs2, off);
        s_sq1  += __shfl_down_sync(0xFFFFFFFF, s_sq1,  off);
        s_sq2  += __shfl_down_sync(0xFFFFFFFF, s_sq2,  off);
    }

    __shared__ float4 warp_sums[THREADS / 32];
    const int wid = tid >> 5;
    const int lid = tid & 31;
    if (lid == 0) warp_sums[wid] = make_float4(s_abs1, s_abs2, s_sq1, s_sq2);
    __syncthreads();

    if (wid == 0) {
        float4 v = (lid < THREADS / 32) ? warp_sums[lid]
                                        : make_float4(0.f, 0.f, 0.f, 0.f);
        #pragma unroll
        for (int off = (THREADS / 64); off > 0; off >>= 1) {
            v.x += __shfl_down_sync(0xFFFFFFFF, v.x, off);
            v.y += __shfl_down_sync(0xFFFFFFFF, v.y, off);
            v.z += __shfl_down_sync(0xFFFFFFFF, v.z, off);
            v.w += __shfl_down_sync(0xFFFFFFFF, v.w, off);
        }
        if (lid == 0) {
            const float l1_1 = v.x, l1_2 = v.y, sse1 = v.z, sse2 = v.w;
            const bool swap = (l1_1 >= l1_2);
            const float near_sse = swap ? sse2 : sse1;
            const float far_sse  = swap ? sse1 : sse2;
            const float la = label[b];
            const float l1 = label[i1];
            const float l2 = label[i2];
            const float near_label = swap ? l2 : l1;
            const float far_label  = swap ? l1 : l2;
            const float dfar  = la - far_label;
            const float dnear = la - near_label;
            const float alpha = dfar * dfar - dnear * dnear;
            const float loss = near_sse - far_sse + alpha * MARGIN;
            if (loss > 0.0f) atomicAdd(out, loss);
        }
    }
}

extern "C" void kernel_launch(void* const* d_in, const int* in_sizes, int n_in,
                              void* d_out, int out_size) {
    const float* feats = (const float*)d_in[0];
    const float* label = (const float*)d_in[1];
    const int*   idx1  = (const int*)d_in[2];
    const int*   idx2  = (const int*)d_in[3];
    float* out = (float*)d_out;

    zero_out_kernel<<<1, 1>>>(out);
    triplet_loss_kernel<<<B_CONST, THREADS>>>(feats, label, idx1, idx2, out);
}